// round 1
// baseline (speedup 1.0000x reference)
#include <cuda_runtime.h>
#include <cstdint>

#define N1 8112
#define N2 2028
#define N3 507
#define NANCH 10647
#define NB 8
#define NC 80
#define KTOP 256
#define CAND 1024
#define MAXPC 100
#define MAXTOT 100
#define SCORE_THR 0.3f
#define IOU_THR 0.5f
#define FINAL_N 8192

// Scratch (device globals: no allocation allowed)
__device__ float  g_sc[NB][NC * MAXPC];
__device__ float4 g_box[NB][NC * MAXPC];
__device__ int    g_cnt[NB][NC];

// SMEM layout sizes (bytes)
#define SMEM1 66208

__global__ __launch_bounds__(256) void nms_class_kernel(
    const float* __restrict__ b1, const float* __restrict__ c1, const float* __restrict__ p1,
    const float* __restrict__ b2, const float* __restrict__ c2, const float* __restrict__ p2,
    const float* __restrict__ b3, const float* __restrict__ c3, const float* __restrict__ p3)
{
    extern __shared__ unsigned char smem[];
    unsigned long long* keys   = reinterpret_cast<unsigned long long*>(smem);        // 1024
    float*   scores   = reinterpret_cast<float*>(keys + CAND);                       // 10648
    float4*  cbox     = reinterpret_cast<float4*>(scores + 10648);                   // 256
    unsigned* supp    = reinterpret_cast<unsigned*>(cbox + 256);                     // 256*8
    float*   csc      = reinterpret_cast<float*>(supp + 2048);                       // 256
    int*     hist     = reinterpret_cast<int*>(csc + 256);                           // 256
    int*     misc     = hist + 256;                                                  // 8
    unsigned* validmask = reinterpret_cast<unsigned*>(misc + 8);                     // 8
    int*     keptslot = reinterpret_cast<int*>(validmask + 8);                       // 256

    const int b = blockIdx.x / NC;
    const int c = blockIdx.x % NC;
    const int tid = threadIdx.x;

    // init
    hist[tid & 255] = 0;
    if (tid == 0) misc[0] = 0;
    if (tid < 8) validmask[tid] = 0;
    __syncthreads();

    // Phase 1: scores + histogram
    for (int a = tid; a < NANCH; a += 256) {
        float conf, cls;
        if (a < N1) {
            int o = b * N1 + a;
            conf = c1[o]; cls = p1[(size_t)o * NC + c];
        } else if (a < N1 + N2) {
            int o = b * N2 + (a - N1);
            conf = c2[o]; cls = p2[(size_t)o * NC + c];
        } else {
            int o = b * N3 + (a - N1 - N2);
            conf = c3[o]; cls = p3[(size_t)o * NC + c];
        }
        float s = conf * cls;
        scores[a] = s;
        int bk = (int)(s * 256.0f);
        bk = bk > 255 ? 255 : bk;
        atomicAdd(&hist[bk], 1);
    }
    __syncthreads();

    // Phase 2: find cut bucket (suffix count >= KTOP)
    if (tid == 0) {
        int acc = 0, bb = 0;
        for (int i = 255; i >= 0; --i) {
            acc += hist[i];
            if (acc >= KTOP) { bb = i; break; }
        }
        misc[1] = bb;
    }
    for (int i = tid; i < CAND; i += 256) keys[i] = 0ull;
    __syncthreads();

    // Phase 3: gather candidates; key = (score_bits<<32) | ~anchor  (ties -> lower index first)
    const int bb = misc[1];
    for (int a = tid; a < NANCH; a += 256) {
        float s = scores[a];
        int bk = (int)(s * 256.0f);
        if (bk > 255) bk = 255;
        if (bk >= bb) {
            int pos = atomicAdd(&misc[0], 1);
            if (pos < CAND)
                keys[pos] = ((unsigned long long)__float_as_uint(s) << 32)
                            | (unsigned)(~(unsigned)a);
        }
    }
    __syncthreads();

    // Phase 4: bitonic sort 1024 keys, descending
    for (int k = 2; k <= CAND; k <<= 1) {
        for (int j = k >> 1; j > 0; j >>= 1) {
            for (int i = tid; i < CAND; i += 256) {
                int ixj = i ^ j;
                if (ixj > i) {
                    unsigned long long va = keys[i], vb = keys[ixj];
                    if ((va < vb) == ((i & k) == 0)) { keys[i] = vb; keys[ixj] = va; }
                }
            }
            __syncthreads();
        }
    }

    // Phase 5: top-256 -> boxes, scores, valid mask
    unsigned long long mykey = keys[tid];
    float sc = __uint_as_float((unsigned)(mykey >> 32));
    unsigned a = ~(unsigned)(mykey & 0xFFFFFFFFu);
    bool valid = (mykey != 0ull) && (sc > SCORE_THR);
    float4 bx;
    {
        const float* bp; size_t off;
        if (a < N1)            { bp = b1; off = (size_t)(b * N1 + a) * 4; }
        else if (a < N1 + N2)  { bp = b2; off = (size_t)(b * N2 + (a - N1)) * 4; }
        else                   { bp = b3; off = (size_t)(b * N3 + (a - N1 - N2)) * 4; }
        bx = *reinterpret_cast<const float4*>(bp + off);
    }
    cbox[tid] = bx;
    csc[tid] = sc;
    __syncthreads();
    if (valid) atomicOr(&validmask[tid >> 5], 1u << (tid & 31));
    __syncthreads();

    // Phase 6: suppression matrix (thread i owns row i; bits j>i with iou>thr)
    {
        const int i = tid;
        const float y1 = bx.x, x1 = bx.y, y2 = bx.z, x2 = bx.w;
        const float areai = (y2 - y1) * (x2 - x1);
        unsigned words[8];
#pragma unroll
        for (int w = 0; w < 8; w++) words[w] = 0u;
        for (int j = i + 1; j < KTOP; j++) {
            float4 bj = cbox[j];
            float areaj = (bj.z - bj.x) * (bj.w - bj.y);
            float iy = fmaxf(fminf(y2, bj.z) - fmaxf(y1, bj.x), 0.0f);
            float ix = fmaxf(fminf(x2, bj.w) - fmaxf(x1, bj.y), 0.0f);
            float inter = iy * ix;
            float uni = areai + areaj - inter;
            float iou = (uni > 0.0f) ? (inter / uni) : 0.0f;
            if (iou > IOU_THR) words[j >> 5] |= (1u << (j & 31));
        }
#pragma unroll
        for (int w = 0; w < 8; w++) supp[i * 8 + w] = words[w];
    }
    __syncthreads();

    // Phase 7: serial greedy scan on warp 0 (lane l<8 owns keep word l)
    if (tid < 32) {
        const int lane = tid;
        unsigned keepw = 0xFFFFFFFFu;
        unsigned vmask = (lane < 8) ? validmask[lane] : 0u;
        int count = 0;
        for (int i = 0; i < KTOP; i++) {
            int owner = i >> 5;
            unsigned kw = __shfl_sync(0xFFFFFFFFu, keepw, owner);
            unsigned vw = __shfl_sync(0xFFFFFFFFu, vmask, owner);
            bool cur = ((kw >> (i & 31)) & 1u) && ((vw >> (i & 31)) & 1u);
            if (cur) {
                if (lane < 8) keepw &= ~supp[i * 8 + lane];
                count++;
                if (lane == 0) keptslot[i] = (count <= MAXPC) ? (count - 1) : -1;
            } else {
                if (lane == 0) keptslot[i] = -1;
            }
        }
        if (lane == 0) g_cnt[b][c] = (count > MAXPC) ? MAXPC : count;
    }
    __syncthreads();

    // write kept entries at deterministic slots
    {
        int r = keptslot[tid];
        if (r >= 0) {
            g_sc[b][c * MAXPC + r]  = csc[tid];
            g_box[b][c * MAXPC + r] = cbox[tid];
        }
    }
}

__global__ __launch_bounds__(1024) void topk_final_kernel(float* __restrict__ out)
{
    extern __shared__ unsigned long long keys2[];  // FINAL_N = 8192
    const int b = blockIdx.x;
    const int tid = threadIdx.x;

    for (int s = tid; s < FINAL_N; s += 1024) {
        unsigned long long key = 0ull;
        if (s < NC * MAXPC) {
            int c = s / MAXPC, r = s - c * MAXPC;
            if (r < g_cnt[b][c]) {
                float sc = g_sc[b][s];
                key = ((unsigned long long)__float_as_uint(sc) << 32)
                      | (unsigned)(~(unsigned)s);
            }
        }
        keys2[s] = key;
    }
    __syncthreads();

    for (int k = 2; k <= FINAL_N; k <<= 1) {
        for (int j = k >> 1; j > 0; j >>= 1) {
            for (int i = tid; i < FINAL_N; i += 1024) {
                int ixj = i ^ j;
                if (ixj > i) {
                    unsigned long long va = keys2[i], vb = keys2[ixj];
                    if ((va < vb) == ((i & k) == 0)) { keys2[i] = vb; keys2[ixj] = va; }
                }
            }
            __syncthreads();
        }
    }

    float* ob = out;                    // [8][100][4]
    float* os = out + NB * MAXTOT * 4;  // [8][100]
    float* oc = os + NB * MAXTOT;       // [8][100]
    float* on = oc + NB * MAXTOT;       // [8]

    if (tid < MAXTOT) {
        unsigned long long key = keys2[tid];
        float sc = 0.0f, cl = 0.0f;
        float bx0 = 0.f, bx1 = 0.f, bx2 = 0.f, bx3 = 0.f;
        if (key != 0ull) {
            sc = __uint_as_float((unsigned)(key >> 32));
            unsigned s = ~(unsigned)(key & 0xFFFFFFFFu);
            cl = (float)(s / MAXPC);
            float4 bb = g_box[b][s];
            bx0 = fminf(fmaxf(bb.x, 0.0f), 1.0f);
            bx1 = fminf(fmaxf(bb.y, 0.0f), 1.0f);
            bx2 = fminf(fmaxf(bb.z, 0.0f), 1.0f);
            bx3 = fminf(fmaxf(bb.w, 0.0f), 1.0f);
        }
        size_t base = (size_t)(b * MAXTOT + tid) * 4;
        ob[base + 0] = bx0; ob[base + 1] = bx1; ob[base + 2] = bx2; ob[base + 3] = bx3;
        os[b * MAXTOT + tid] = sc;
        oc[b * MAXTOT + tid] = cl;
    }
    if (tid == 0) {
        int tot = 0;
        for (int c = 0; c < NC; c++) tot += g_cnt[b][c];
        on[b] = (float)(tot > MAXTOT ? MAXTOT : tot);
    }
}

extern "C" void kernel_launch(void* const* d_in, const int* in_sizes, int n_in,
                              void* d_out, int out_size)
{
    const float* b1 = (const float*)d_in[0];
    const float* c1 = (const float*)d_in[1];
    const float* p1 = (const float*)d_in[2];
    const float* b2 = (const float*)d_in[3];
    const float* c2 = (const float*)d_in[4];
    const float* p2 = (const float*)d_in[5];
    const float* b3 = (const float*)d_in[6];
    const float* c3 = (const float*)d_in[7];
    const float* p3 = (const float*)d_in[8];

    cudaFuncSetAttribute(nms_class_kernel,
                         cudaFuncAttributeMaxDynamicSharedMemorySize, SMEM1);
    cudaFuncSetAttribute(topk_final_kernel,
                         cudaFuncAttributeMaxDynamicSharedMemorySize, FINAL_N * 8);

    nms_class_kernel<<<NB * NC, 256, SMEM1>>>(b1, c1, p1, b2, c2, p2, b3, c3, p3);
    topk_final_kernel<<<NB, 1024, FINAL_N * 8>>>((float*)d_out);
}

// round 2
// speedup vs baseline: 2.2806x; 2.2806x over previous
#include <cuda_runtime.h>
#include <cstdint>

#define N1 8112
#define N2 2028
#define N3 507
#define NANCH 10647
#define NANCH_P 10656
#define NB 8
#define NC 80
#define KTOP 256
#define CAND 512
#define MAXPC 100
#define MAXTOT 100
#define SCORE_THR 0.3f
#define IOU_THR 0.5f
#define TILE_A 128

// Scratch (device globals: no allocation allowed)
__device__ float  g_scoresT[NB][NC][NANCH_P];   // ~27.3 MB, coalesced per (b,c)
__device__ float  g_sc[NB][NC * MAXPC];
__device__ float4 g_box[NB][NC * MAXPC];
__device__ int    g_cnt[NB][NC];

// ---------------------------------------------------------------------------
// Kernel 0: coalesced score compute + transpose.
// Reads p (class-innermost, contiguous) and conf, writes scoresT[b][c][a]
// so the NMS kernel gets fully coalesced per-class score rows.
// ---------------------------------------------------------------------------
__global__ __launch_bounds__(256) void score_transpose_kernel(
    const float* __restrict__ c1, const float* __restrict__ p1,
    const float* __restrict__ c2, const float* __restrict__ p2,
    const float* __restrict__ c3, const float* __restrict__ p3)
{
    __shared__ float conf_s[TILE_A];
    __shared__ float tile[TILE_A][NC + 1];   // +1 pad: conflict-free transpose

    const int b   = blockIdx.y;
    const int t0  = blockIdx.x * TILE_A;
    const int tid = threadIdx.x;

    if (tid < TILE_A) {
        int a = t0 + tid;
        float cv = 0.0f;
        if (a < NANCH) {
            if (a < N1)           cv = c1[b * N1 + a];
            else if (a < N1 + N2) cv = c2[b * N2 + (a - N1)];
            else                  cv = c3[b * N3 + (a - N1 - N2)];
        }
        conf_s[tid] = cv;
    }
    __syncthreads();

    // load: consecutive tid -> consecutive class index -> coalesced p reads
    for (int idx = tid; idx < TILE_A * NC; idx += 256) {
        int al = idx / NC;
        int c  = idx - al * NC;
        int a  = t0 + al;
        float v = 0.0f;
        if (a < NANCH) {
            const float* pp; int o;
            if (a < N1)           { pp = p1; o = b * N1 + a; }
            else if (a < N1 + N2) { pp = p2; o = b * N2 + (a - N1); }
            else                  { pp = p3; o = b * N3 + (a - N1 - N2); }
            v = pp[(size_t)o * NC + c] * conf_s[al];
        }
        tile[al][c] = v;
    }
    __syncthreads();

    // store: consecutive tid -> consecutive anchor -> coalesced writes
    for (int idx = tid; idx < NC * TILE_A; idx += 256) {
        int c  = idx / TILE_A;
        int al = idx - c * TILE_A;
        int a  = t0 + al;
        if (a < NANCH) g_scoresT[b][c][a] = tile[al][c];
    }
}

// ---------------------------------------------------------------------------
// Kernel 1: per-(image,class) NMS. One block of 256 threads per task.
// ~19.5 KB smem -> 8 blocks/SM -> all 640 blocks in a single wave.
// ---------------------------------------------------------------------------
__global__ __launch_bounds__(256) void nms_class_kernel(
    const float* __restrict__ b1, const float* __restrict__ b2,
    const float* __restrict__ b3)
{
    __shared__ unsigned long long keys[CAND];
    __shared__ float4 cbox[KTOP];
    __shared__ __align__(16) unsigned supp[KTOP * 8];
    __shared__ float csc[KTOP];
    __shared__ int hist[256];
    __shared__ int misc[4];
    __shared__ __align__(16) unsigned validm[8];
    __shared__ int keptslot[KTOP];

    const int b   = blockIdx.x / NC;
    const int c   = blockIdx.x % NC;
    const int tid = threadIdx.x;

    hist[tid] = 0;
    if (tid == 0) misc[0] = 0;
    keys[tid] = 0ull;
    keys[tid + 256] = 0ull;
    __syncthreads();

    // Phase 1: histogram of scores > THR over 256 buckets of (s-0.3)
    const float* srow = &g_scoresT[b][c][0];
#pragma unroll 6
    for (int a = tid; a < NANCH; a += 256) {
        float s = srow[a];
        if (s > SCORE_THR) {
            int bk = (int)((s - SCORE_THR) * (256.0f / 0.7f));
            bk = bk > 255 ? 255 : (bk < 0 ? 0 : bk);
            atomicAdd(&hist[bk], 1);
        }
    }
    __syncthreads();

    // Phase 2: warp 0 finds cut bucket (largest bb with suffix >= KTOP)
    if (tid < 32) {
        int partial = 0;
#pragma unroll
        for (int k2 = 0; k2 < 8; k2++) partial += hist[tid * 8 + k2];
        int suf = partial;
#pragma unroll
        for (int off = 1; off < 32; off <<= 1) {
            int v = __shfl_down_sync(0xFFFFFFFFu, suf, off);
            if (tid + off < 32) suf += v;
        }
        unsigned bal = __ballot_sync(0xFFFFFFFFu, suf >= KTOP);
        if (bal != 0) {
            int g = 31 - __clz(bal);
            int base = (g < 31) ? __shfl_sync(0xFFFFFFFFu, suf, g + 1) : 0;
            if (tid == 0) {
                int acc = base, bb = 8 * g;
                for (int k2 = 7; k2 >= 0; k2--) {
                    acc += hist[8 * g + k2];
                    if (acc >= KTOP) { bb = 8 * g + k2; break; }
                }
                misc[1] = bb;
            }
        } else if (tid == 0) {
            misc[1] = 0;  // fewer than KTOP above threshold: take all
        }
    }
    __syncthreads();

    // Phase 3: gather candidates. key = score_bits<<32 | ~anchor (tie->lower idx)
    const int bb = misc[1];
#pragma unroll 6
    for (int a = tid; a < NANCH; a += 256) {
        float s = srow[a];
        if (s > SCORE_THR) {
            int bk = (int)((s - SCORE_THR) * (256.0f / 0.7f));
            bk = bk > 255 ? 255 : (bk < 0 ? 0 : bk);
            if (bk >= bb) {
                int pos = atomicAdd(&misc[0], 1);
                if (pos < CAND)
                    keys[pos] = ((unsigned long long)__float_as_uint(s) << 32)
                                | (unsigned)(~(unsigned)a);
            }
        }
    }
    __syncthreads();

    // Phase 4: bitonic sort 512 keys descending (256 comparators/stage)
    for (int k = 2; k <= CAND; k <<= 1) {
        for (int j = k >> 1; j > 0; j >>= 1) {
            int i = ((tid & ~(j - 1)) << 1) | (tid & (j - 1));
            int p = i | j;
            unsigned long long va = keys[i], vb = keys[p];
            if ((va < vb) == ((i & k) == 0)) { keys[i] = vb; keys[p] = va; }
            __syncthreads();
        }
    }

    // Phase 5: top-256 -> boxes/scores/valid
    unsigned long long mykey = keys[tid];
    bool valid = (mykey != 0ull);
    float sc = __uint_as_float((unsigned)(mykey >> 32));
    float4 bx = make_float4(0.f, 0.f, 0.f, 0.f);
    if (valid) {
        unsigned a = ~(unsigned)(mykey & 0xFFFFFFFFu);
        const float* bp; size_t off;
        if (a < N1)           { bp = b1; off = (size_t)(b * N1 + a) * 4; }
        else if (a < N1 + N2) { bp = b2; off = (size_t)(b * N2 + (a - N1)) * 4; }
        else                  { bp = b3; off = (size_t)(b * N3 + (a - N1 - N2)) * 4; }
        bx = *reinterpret_cast<const float4*>(bp + off);
    }
    cbox[tid] = bx;
    csc[tid]  = sc;
    keptslot[tid] = -1;
    {
        unsigned bal = __ballot_sync(0xFFFFFFFFu, valid);
        if ((tid & 31) == 0) validm[tid >> 5] = bal;
    }
    __syncthreads();

    // Phase 6: suppression bitmask matrix (row i: bits j>i with iou>thr)
    {
        const int i = tid;
        const float y1 = bx.x, x1 = bx.y, y2 = bx.z, x2 = bx.w;
        const float areai = (y2 - y1) * (x2 - x1);
        unsigned words[8];
#pragma unroll
        for (int w = 0; w < 8; w++) words[w] = 0u;
        for (int j = i + 1; j < KTOP; j++) {
            float4 bj = cbox[j];
            float areaj = (bj.z - bj.x) * (bj.w - bj.y);
            float iy = fmaxf(fminf(y2, bj.z) - fmaxf(y1, bj.x), 0.0f);
            float ix = fmaxf(fminf(x2, bj.w) - fmaxf(x1, bj.y), 0.0f);
            float inter = iy * ix;
            float uni = (areai + areaj) - inter;
            // exact-safe filter: inter <= 0.4*uni  =>  fl(inter/uni) < 0.5
            if (inter > 0.4f * uni) {
                float iou = inter / uni;
                if (iou > IOU_THR) words[j >> 5] |= (1u << (j & 31));
            }
        }
#pragma unroll
        for (int w = 0; w < 8; w++) supp[i * 8 + w] = words[w];
    }
    __syncthreads();

    // Phase 7: greedy scan, single thread, register-resident keep bitmask
    if (tid == 0) {
        unsigned k0 = validm[0], k1 = validm[1], k2 = validm[2], k3 = validm[3];
        unsigned k4 = validm[4], k5 = validm[5], k6 = validm[6], k7 = validm[7];
        int count = 0;
#pragma unroll
        for (int w = 0; w < 8; w++) {
            unsigned kw;
            switch (w) {
                case 0: kw = k0; break; case 1: kw = k1; break;
                case 2: kw = k2; break; case 3: kw = k3; break;
                case 4: kw = k4; break; case 5: kw = k5; break;
                case 6: kw = k6; break; default: kw = k7; break;
            }
            unsigned cw = kw;
            while (cw) {
                int bit = __ffs(cw) - 1;
                int i = (w << 5) + bit;
                count++;
                if (count <= MAXPC) keptslot[i] = count - 1;
                uint4 r0 = *reinterpret_cast<const uint4*>(&supp[i * 8]);
                uint4 r1 = *reinterpret_cast<const uint4*>(&supp[i * 8 + 4]);
                k0 &= ~r0.x; k1 &= ~r0.y; k2 &= ~r0.z; k3 &= ~r0.w;
                k4 &= ~r1.x; k5 &= ~r1.y; k6 &= ~r1.z; k7 &= ~r1.w;
                unsigned above = (bit == 31) ? 0u : (0xFFFFFFFFu << (bit + 1));
                switch (w) {
                    case 0: kw = k0; break; case 1: kw = k1; break;
                    case 2: kw = k2; break; case 3: kw = k3; break;
                    case 4: kw = k4; break; case 5: kw = k5; break;
                    case 6: kw = k6; break; default: kw = k7; break;
                }
                cw = kw & above;
            }
        }
        g_cnt[b][c] = (count > MAXPC) ? MAXPC : count;
    }
    __syncthreads();

    {
        int r = keptslot[tid];
        if (r >= 0) {
            g_sc[b][c * MAXPC + r]  = csc[tid];
            g_box[b][c * MAXPC + r] = cbox[tid];
        }
    }
}

// ---------------------------------------------------------------------------
// Kernel 2: per-image top-100 via histogram threshold + small sort.
// ---------------------------------------------------------------------------
#define FBINS 2048
#define FCAND 512

__global__ __launch_bounds__(1024) void topk_final_kernel(float* __restrict__ out)
{
    __shared__ int cnt_s[NC];
    __shared__ int hist2[FBINS];
    __shared__ unsigned long long keys2[FCAND];
    __shared__ int gsum[64];
    __shared__ int misc2[4];

    const int b   = blockIdx.x;
    const int tid = threadIdx.x;

    if (tid < NC) cnt_s[tid] = g_cnt[b][tid];
    hist2[tid] = 0;
    hist2[tid + 1024] = 0;
    if (tid < FCAND) keys2[tid] = 0ull;
    __syncthreads();

    // histogram of kept scores (all > 0.3 by construction)
#pragma unroll
    for (int k = 0; k < 8; k++) {
        int s_idx = tid + k * 1024;
        if (s_idx < NC * MAXPC) {
            int c = s_idx / MAXPC, r = s_idx - c * MAXPC;
            if (r < cnt_s[c]) {
                float sc = g_sc[b][s_idx];
                int bk = (int)((sc - SCORE_THR) * ((float)FBINS / 0.7f));
                bk = bk > FBINS - 1 ? FBINS - 1 : (bk < 0 ? 0 : bk);
                atomicAdd(&hist2[bk], 1);
            }
        }
    }
    __syncthreads();

    if (tid < 64) {
        int s = 0;
#pragma unroll
        for (int k = 0; k < 32; k++) s += hist2[tid * 32 + k];
        gsum[tid] = s;
    }
    __syncthreads();
    if (tid == 0) {
        int acc = 0, g = -1, bbv = 0;
        for (int i = 63; i >= 0; i--) {
            if (acc + gsum[i] >= MAXTOT) { g = i; break; }
            acc += gsum[i];
        }
        if (g >= 0) {
            for (int k = 31; k >= 0; k--) {
                acc += hist2[g * 32 + k];
                if (acc >= MAXTOT) { bbv = g * 32 + k; break; }
            }
        }
        misc2[1] = bbv;
        misc2[0] = 0;
    }
    __syncthreads();

    const int bb = misc2[1];
#pragma unroll
    for (int k = 0; k < 8; k++) {
        int s_idx = tid + k * 1024;
        if (s_idx < NC * MAXPC) {
            int c = s_idx / MAXPC, r = s_idx - c * MAXPC;
            if (r < cnt_s[c]) {
                float sc = g_sc[b][s_idx];
                int bk = (int)((sc - SCORE_THR) * ((float)FBINS / 0.7f));
                bk = bk > FBINS - 1 ? FBINS - 1 : (bk < 0 ? 0 : bk);
                if (bk >= bb) {
                    int pos = atomicAdd(&misc2[0], 1);
                    if (pos < FCAND)
                        keys2[pos] = ((unsigned long long)__float_as_uint(sc) << 32)
                                     | (unsigned)(~(unsigned)s_idx);
                }
            }
        }
    }
    __syncthreads();

    // bitonic sort 512, descending; 256 comparators, all threads hit barriers
    for (int k = 2; k <= FCAND; k <<= 1) {
        for (int j = k >> 1; j > 0; j >>= 1) {
            if (tid < FCAND / 2) {
                int i = ((tid & ~(j - 1)) << 1) | (tid & (j - 1));
                int p = i | j;
                unsigned long long va = keys2[i], vb = keys2[p];
                if ((va < vb) == ((i & k) == 0)) { keys2[i] = vb; keys2[p] = va; }
            }
            __syncthreads();
        }
    }

    float* ob = out;                    // [8][100][4]
    float* os = out + NB * MAXTOT * 4;  // [8][100]
    float* oc = os + NB * MAXTOT;       // [8][100]
    float* on = oc + NB * MAXTOT;       // [8]

    if (tid < MAXTOT) {
        unsigned long long key = keys2[tid];
        float sc = 0.0f, cl = 0.0f;
        float bx0 = 0.f, bx1 = 0.f, bx2 = 0.f, bx3 = 0.f;
        if (key != 0ull) {
            sc = __uint_as_float((unsigned)(key >> 32));
            unsigned s = ~(unsigned)(key & 0xFFFFFFFFu);
            cl = (float)(s / MAXPC);
            float4 bbx = g_box[b][s];
            bx0 = fminf(fmaxf(bbx.x, 0.0f), 1.0f);
            bx1 = fminf(fmaxf(bbx.y, 0.0f), 1.0f);
            bx2 = fminf(fmaxf(bbx.z, 0.0f), 1.0f);
            bx3 = fminf(fmaxf(bbx.w, 0.0f), 1.0f);
        }
        size_t base = (size_t)(b * MAXTOT + tid) * 4;
        ob[base + 0] = bx0; ob[base + 1] = bx1; ob[base + 2] = bx2; ob[base + 3] = bx3;
        os[b * MAXTOT + tid] = sc;
        oc[b * MAXTOT + tid] = cl;
    }
    if (tid == 0) {
        int tot = 0;
        for (int c = 0; c < NC; c++) tot += cnt_s[c];
        on[b] = (float)(tot > MAXTOT ? MAXTOT : tot);
    }
}

extern "C" void kernel_launch(void* const* d_in, const int* in_sizes, int n_in,
                              void* d_out, int out_size)
{
    const float* b1 = (const float*)d_in[0];
    const float* c1 = (const float*)d_in[1];
    const float* p1 = (const float*)d_in[2];
    const float* b2 = (const float*)d_in[3];
    const float* c2 = (const float*)d_in[4];
    const float* p2 = (const float*)d_in[5];
    const float* b3 = (const float*)d_in[6];
    const float* c3 = (const float*)d_in[7];
    const float* p3 = (const float*)d_in[8];

    dim3 tgrid((NANCH + TILE_A - 1) / TILE_A, NB);
    score_transpose_kernel<<<tgrid, 256>>>(c1, p1, c2, p2, c3, p3);
    nms_class_kernel<<<NB * NC, 256>>>(b1, b2, b3);
    topk_final_kernel<<<NB, 1024>>>((float*)d_out);
}

// round 3
// speedup vs baseline: 2.3366x; 1.0246x over previous
#include <cuda_runtime.h>
#include <cstdint>

#define N1 8112
#define N2 2028
#define N3 507
#define NANCH 10647
#define NANCH_P 10656
#define NVEC4 (NANCH_P / 4)        /* 2664 */
#define NVEC4_PAD 2816             /* 11 * 256, uniform warp trips */
#define NB 8
#define NC 80
#define KTOP 256
#define CAND 512
#define CBUF 4096
#define MAXPC 100
#define MAXTOT 100
#define SCORE_THR 0.3f
#define IOU_THR 0.5f
#define TILE_A 128

// Scratch (device globals: no allocation allowed)
__device__ float  g_scoresT[NB][NC][NANCH_P];   // ~27.3 MB, coalesced per (b,c)
__device__ float  g_sc[NB][NC * MAXPC];
__device__ float4 g_box[NB][NC * MAXPC];
__device__ int    g_cnt[NB][NC];

// ---------------------------------------------------------------------------
// Kernel 0: coalesced score compute + transpose (float4 LDG).
// ---------------------------------------------------------------------------
__global__ __launch_bounds__(256) void score_transpose_kernel(
    const float* __restrict__ c1, const float* __restrict__ p1,
    const float* __restrict__ c2, const float* __restrict__ p2,
    const float* __restrict__ c3, const float* __restrict__ p3)
{
    __shared__ float conf_s[TILE_A];
    __shared__ float tile[TILE_A][NC + 1];   // odd row stride -> conflict-free col reads

    const int b   = blockIdx.y;
    const int t0  = blockIdx.x * TILE_A;
    const int tid = threadIdx.x;

    if (tid < TILE_A) {
        int a = t0 + tid;
        float cv = 0.0f;
        if (a < NANCH) {
            if (a < N1)           cv = c1[b * N1 + a];
            else if (a < N1 + N2) cv = c2[b * N2 + (a - N1)];
            else                  cv = c3[b * N3 + (a - N1 - N2)];
        }
        conf_s[tid] = cv;
    }
    __syncthreads();

    // load: 128 anchors x 20 float4 = 2560 vec loads, coalesced
    for (int idx = tid; idx < TILE_A * (NC / 4); idx += 256) {
        int al = idx / (NC / 4);
        int q  = idx - al * (NC / 4);
        int a  = t0 + al;
        float4 v = make_float4(0.f, 0.f, 0.f, 0.f);
        if (a < NANCH) {
            const float* pp; int o;
            if (a < N1)           { pp = p1; o = b * N1 + a; }
            else if (a < N1 + N2) { pp = p2; o = b * N2 + (a - N1); }
            else                  { pp = p3; o = b * N3 + (a - N1 - N2); }
            v = *reinterpret_cast<const float4*>(pp + (size_t)o * NC + q * 4);
        }
        float cf = conf_s[al];
        tile[al][q * 4 + 0] = v.x * cf;
        tile[al][q * 4 + 1] = v.y * cf;
        tile[al][q * 4 + 2] = v.z * cf;
        tile[al][q * 4 + 3] = v.w * cf;
    }
    __syncthreads();

    // store: consecutive tid -> consecutive anchor -> coalesced STG
    for (int idx = tid; idx < NC * TILE_A; idx += 256) {
        int c  = idx >> 7;
        int al = idx & (TILE_A - 1);
        int a  = t0 + al;
        if (a < NANCH) g_scoresT[b][c][a] = tile[al][c];
    }
}

// ---------------------------------------------------------------------------
// Kernel 1: per-(image,class) NMS. One global pass; smem candidate buffer.
// ---------------------------------------------------------------------------
__global__ __launch_bounds__(256) void nms_class_kernel(
    const float* __restrict__ b1, const float* __restrict__ b2,
    const float* __restrict__ b3)
{
    // union buffer: candidates (phases 1-3), then box/area/supp (phases 5-7)
    __shared__ __align__(16) unsigned char ubuf[CBUF * 8];   // 32 KB
    __shared__ unsigned long long keys[CAND];                 // 4 KB
    __shared__ int hist[256];
    __shared__ int misc[4];
    __shared__ unsigned validm[8];

    unsigned long long* cand = reinterpret_cast<unsigned long long*>(ubuf);
    float4*   cbox  = reinterpret_cast<float4*>(ubuf);                     // 4 KB
    float*    csc   = reinterpret_cast<float*>(ubuf + 4096);               // 1 KB
    float*    carea = reinterpret_cast<float*>(ubuf + 5120);               // 1 KB
    unsigned* supp  = reinterpret_cast<unsigned*>(ubuf + 6144);            // 8 KB
    int*   keptslot = reinterpret_cast<int*>(ubuf + 14336);                // 1 KB

    const int b    = blockIdx.x / NC;
    const int c    = blockIdx.x % NC;
    const int tid  = threadIdx.x;
    const int lane = tid & 31;
    const unsigned ltmask = (1u << lane) - 1u;

    hist[tid] = 0;
    if (tid == 0) { misc[0] = 0; misc[2] = 0; }
    keys[tid] = 0ull;
    keys[tid + 256] = 0ull;
    __syncthreads();

    // Phase 1: single pass: histogram + warp-aggregated candidate append
    const float4* srow4 =
        reinterpret_cast<const float4*>(&g_scoresT[b][c][0]);
    for (int it = tid; it < NVEC4_PAD; it += 256) {
        float4 v = make_float4(0.f, 0.f, 0.f, 0.f);
        if (it < NVEC4) v = srow4[it];
        float sv[4] = {v.x, v.y, v.z, v.w};
#pragma unroll
        for (int k = 0; k < 4; k++) {
            float s = sv[k];
            bool pred = s > SCORE_THR;
            unsigned m = __ballot_sync(0xFFFFFFFFu, pred);
            if (pred) {
                int bk = (int)((s - SCORE_THR) * (256.0f / 0.7f));
                bk = bk > 255 ? 255 : (bk < 0 ? 0 : bk);
                atomicAdd(&hist[bk], 1);
                int rank = __popc(m & ltmask);
                int base;
                if (rank == 0) base = atomicAdd(&misc[0], __popc(m));
                base = __shfl_sync(m, base, __ffs(m) - 1);
                int pos = base + rank;
                unsigned a = (unsigned)(it * 4 + k);
                if (pos < CBUF)
                    cand[pos] = ((unsigned long long)__float_as_uint(s) << 32)
                                | (unsigned)(~a);
            }
        }
    }
    __syncthreads();

    // Phase 2: warp 0 finds cut bucket (largest bb with suffix >= KTOP)
    if (tid < 32) {
        int partial = 0;
#pragma unroll
        for (int k2 = 0; k2 < 8; k2++) partial += hist[tid * 8 + k2];
        int suf = partial;
#pragma unroll
        for (int off = 1; off < 32; off <<= 1) {
            int v = __shfl_down_sync(0xFFFFFFFFu, suf, off);
            if (tid + off < 32) suf += v;
        }
        unsigned bal = __ballot_sync(0xFFFFFFFFu, suf >= KTOP);
        if (bal != 0) {
            int g = 31 - __clz(bal);
            int basev = (g < 31) ? __shfl_sync(0xFFFFFFFFu, suf, g + 1) : 0;
            if (tid == 0) {
                int acc = basev, bb = 8 * g;
                for (int k2 = 7; k2 >= 0; k2--) {
                    acc += hist[8 * g + k2];
                    if (acc >= KTOP) { bb = 8 * g + k2; break; }
                }
                misc[1] = bb;
            }
        } else if (tid == 0) {
            misc[1] = 0;  // fewer than KTOP candidates: take all
        }
    }
    __syncthreads();

    // Phase 3: select from smem candidate list into keys[]
    const int bb  = misc[1];
    const int cnt = misc[0] < CBUF ? misc[0] : CBUF;
    const int cntp = (cnt + 255) & ~255;
    for (int it = tid; it < cntp; it += 256) {
        unsigned long long key = (it < cnt) ? cand[it] : 0ull;
        float s = __uint_as_float((unsigned)(key >> 32));
        bool pred = false;
        if (it < cnt) {
            int bk = (int)((s - SCORE_THR) * (256.0f / 0.7f));
            bk = bk > 255 ? 255 : (bk < 0 ? 0 : bk);
            pred = (bk >= bb);
        }
        unsigned m = __ballot_sync(0xFFFFFFFFu, pred);
        if (pred) {
            int rank = __popc(m & ltmask);
            int base;
            if (rank == 0) base = atomicAdd(&misc[2], __popc(m));
            base = __shfl_sync(m, base, __ffs(m) - 1);
            int pos = base + rank;
            if (pos < CAND) keys[pos] = key;
        }
    }
    __syncthreads();

    // Phase 4: bitonic sort 512 keys descending (256 comparators/stage)
    for (int k = 2; k <= CAND; k <<= 1) {
        for (int j = k >> 1; j > 0; j >>= 1) {
            int i = ((tid & ~(j - 1)) << 1) | (tid & (j - 1));
            int p = i | j;
            unsigned long long va = keys[i], vb = keys[p];
            if ((va < vb) == ((i & k) == 0)) { keys[i] = vb; keys[p] = va; }
            __syncthreads();
        }
    }

    // Phase 5: top-256 -> boxes/scores/areas/valid (cand buffer now dead)
    unsigned long long mykey = keys[tid];
    bool valid = (mykey != 0ull);
    float sc = __uint_as_float((unsigned)(mykey >> 32));
    float4 bx = make_float4(0.f, 0.f, 0.f, 0.f);
    if (valid) {
        unsigned a = ~(unsigned)(mykey & 0xFFFFFFFFu);
        const float* bp; size_t off;
        if (a < N1)           { bp = b1; off = (size_t)(b * N1 + a) * 4; }
        else if (a < N1 + N2) { bp = b2; off = (size_t)(b * N2 + (a - N1)) * 4; }
        else                  { bp = b3; off = (size_t)(b * N3 + (a - N1 - N2)) * 4; }
        bx = *reinterpret_cast<const float4*>(bp + off);
    }
    __syncthreads();   // ensure all reads of keys done before ubuf reuse... (keys separate; sync for cand death)
    cbox[tid]  = bx;
    csc[tid]   = sc;
    carea[tid] = (bx.z - bx.x) * (bx.w - bx.y);
    keptslot[tid] = -1;
    {
        unsigned bal = __ballot_sync(0xFFFFFFFFu, valid);
        if (lane == 0) validm[tid >> 5] = bal;
    }
    __syncthreads();

    // Phase 6: suppression bitmask matrix (row i: bits j>i with iou>thr)
    {
        const int i = tid;
        const float y1 = bx.x, x1 = bx.y, y2 = bx.z, x2 = bx.w;
        const float areai = carea[i];
        unsigned words[8];
#pragma unroll
        for (int w = 0; w < 8; w++) words[w] = 0u;
        if (valid) {
#pragma unroll 4
            for (int j = i + 1; j < KTOP; j++) {
                float4 bj = cbox[j];
                float aj = carea[j];
                float iy = fmaxf(fminf(y2, bj.z) - fmaxf(y1, bj.x), 0.0f);
                float ix = fmaxf(fminf(x2, bj.w) - fmaxf(x1, bj.y), 0.0f);
                float inter = iy * ix;
                float uni = (areai + aj) - inter;
                // exact-safe filter: inter <= 0.4*uni => fl(inter/uni) < 0.5
                if (inter > 0.4f * uni) {
                    float iou = inter / uni;
                    if (iou > IOU_THR) words[j >> 5] |= (1u << (j & 31));
                }
            }
        }
        uint4* sp = reinterpret_cast<uint4*>(&supp[i * 8]);
        sp[0] = make_uint4(words[0], words[1], words[2], words[3]);
        sp[1] = make_uint4(words[4], words[5], words[6], words[7]);
    }
    __syncthreads();

    // Phase 7: greedy scan, single thread, register-resident keep bitmask
    if (tid == 0) {
        unsigned k0 = validm[0], k1 = validm[1], k2 = validm[2], k3 = validm[3];
        unsigned k4 = validm[4], k5 = validm[5], k6 = validm[6], k7 = validm[7];
        int count = 0;
#pragma unroll
        for (int w = 0; w < 8; w++) {
            unsigned kw;
            switch (w) {
                case 0: kw = k0; break; case 1: kw = k1; break;
                case 2: kw = k2; break; case 3: kw = k3; break;
                case 4: kw = k4; break; case 5: kw = k5; break;
                case 6: kw = k6; break; default: kw = k7; break;
            }
            unsigned cw = kw;
            while (cw) {
                int bit = __ffs(cw) - 1;
                int i = (w << 5) + bit;
                count++;
                if (count <= MAXPC) keptslot[i] = count - 1;
                uint4 r0 = *reinterpret_cast<const uint4*>(&supp[i * 8]);
                uint4 r1 = *reinterpret_cast<const uint4*>(&supp[i * 8 + 4]);
                k0 &= ~r0.x; k1 &= ~r0.y; k2 &= ~r0.z; k3 &= ~r0.w;
                k4 &= ~r1.x; k5 &= ~r1.y; k6 &= ~r1.z; k7 &= ~r1.w;
                unsigned above = (bit == 31) ? 0u : (0xFFFFFFFFu << (bit + 1));
                switch (w) {
                    case 0: kw = k0; break; case 1: kw = k1; break;
                    case 2: kw = k2; break; case 3: kw = k3; break;
                    case 4: kw = k4; break; case 5: kw = k5; break;
                    case 6: kw = k6; break; default: kw = k7; break;
                }
                cw = kw & above;
            }
        }
        g_cnt[b][c] = (count > MAXPC) ? MAXPC : count;
    }
    __syncthreads();

    {
        int r = keptslot[tid];
        if (r >= 0) {
            g_sc[b][c * MAXPC + r]  = csc[tid];
            g_box[b][c * MAXPC + r] = cbox[tid];
        }
    }
}

// ---------------------------------------------------------------------------
// Kernel 2: per-image top-100 via histogram threshold + small sort.
// ---------------------------------------------------------------------------
#define FBINS 2048
#define FCAND 512

__global__ __launch_bounds__(1024) void topk_final_kernel(float* __restrict__ out)
{
    __shared__ int cnt_s[NC];
    __shared__ int hist2[FBINS];
    __shared__ unsigned long long keys2[FCAND];
    __shared__ int gsum[64];
    __shared__ int misc2[4];

    const int b   = blockIdx.x;
    const int tid = threadIdx.x;

    if (tid < NC) cnt_s[tid] = g_cnt[b][tid];
    hist2[tid] = 0;
    hist2[tid + 1024] = 0;
    if (tid < FCAND) keys2[tid] = 0ull;
    __syncthreads();

#pragma unroll
    for (int k = 0; k < 8; k++) {
        int s_idx = tid + k * 1024;
        if (s_idx < NC * MAXPC) {
            int c = s_idx / MAXPC, r = s_idx - c * MAXPC;
            if (r < cnt_s[c]) {
                float sc = g_sc[b][s_idx];
                int bk = (int)((sc - SCORE_THR) * ((float)FBINS / 0.7f));
                bk = bk > FBINS - 1 ? FBINS - 1 : (bk < 0 ? 0 : bk);
                atomicAdd(&hist2[bk], 1);
            }
        }
    }
    __syncthreads();

    if (tid < 64) {
        int s = 0;
#pragma unroll
        for (int k = 0; k < 32; k++) s += hist2[tid * 32 + k];
        gsum[tid] = s;
    }
    __syncthreads();
    if (tid == 0) {
        int acc = 0, g = -1, bbv = 0;
        for (int i = 63; i >= 0; i--) {
            if (acc + gsum[i] >= MAXTOT) { g = i; break; }
            acc += gsum[i];
        }
        if (g >= 0) {
            for (int k = 31; k >= 0; k--) {
                acc += hist2[g * 32 + k];
                if (acc >= MAXTOT) { bbv = g * 32 + k; break; }
            }
        }
        misc2[1] = bbv;
        misc2[0] = 0;
    }
    __syncthreads();

    const int bb = misc2[1];
#pragma unroll
    for (int k = 0; k < 8; k++) {
        int s_idx = tid + k * 1024;
        if (s_idx < NC * MAXPC) {
            int c = s_idx / MAXPC, r = s_idx - c * MAXPC;
            if (r < cnt_s[c]) {
                float sc = g_sc[b][s_idx];
                int bk = (int)((sc - SCORE_THR) * ((float)FBINS / 0.7f));
                bk = bk > FBINS - 1 ? FBINS - 1 : (bk < 0 ? 0 : bk);
                if (bk >= bb) {
                    int pos = atomicAdd(&misc2[0], 1);
                    if (pos < FCAND)
                        keys2[pos] = ((unsigned long long)__float_as_uint(sc) << 32)
                                     | (unsigned)(~(unsigned)s_idx);
                }
            }
        }
    }
    __syncthreads();

    for (int k = 2; k <= FCAND; k <<= 1) {
        for (int j = k >> 1; j > 0; j >>= 1) {
            if (tid < FCAND / 2) {
                int i = ((tid & ~(j - 1)) << 1) | (tid & (j - 1));
                int p = i | j;
                unsigned long long va = keys2[i], vb = keys2[p];
                if ((va < vb) == ((i & k) == 0)) { keys2[i] = vb; keys2[p] = va; }
            }
            __syncthreads();
        }
    }

    float* ob = out;                    // [8][100][4]
    float* os = out + NB * MAXTOT * 4;  // [8][100]
    float* oc = os + NB * MAXTOT;       // [8][100]
    float* on = oc + NB * MAXTOT;       // [8]

    if (tid < MAXTOT) {
        unsigned long long key = keys2[tid];
        float sc = 0.0f, cl = 0.0f;
        float bx0 = 0.f, bx1 = 0.f, bx2 = 0.f, bx3 = 0.f;
        if (key != 0ull) {
            sc = __uint_as_float((unsigned)(key >> 32));
            unsigned s = ~(unsigned)(key & 0xFFFFFFFFu);
            cl = (float)(s / MAXPC);
            float4 bbx = g_box[b][s];
            bx0 = fminf(fmaxf(bbx.x, 0.0f), 1.0f);
            bx1 = fminf(fmaxf(bbx.y, 0.0f), 1.0f);
            bx2 = fminf(fmaxf(bbx.z, 0.0f), 1.0f);
            bx3 = fminf(fmaxf(bbx.w, 0.0f), 1.0f);
        }
        size_t base = (size_t)(b * MAXTOT + tid) * 4;
        ob[base + 0] = bx0; ob[base + 1] = bx1; ob[base + 2] = bx2; ob[base + 3] = bx3;
        os[b * MAXTOT + tid] = sc;
        oc[b * MAXTOT + tid] = cl;
    }
    if (tid == 0) {
        int tot = 0;
        for (int c = 0; c < NC; c++) tot += cnt_s[c];
        on[b] = (float)(tot > MAXTOT ? MAXTOT : tot);
    }
}

extern "C" void kernel_launch(void* const* d_in, const int* in_sizes, int n_in,
                              void* d_out, int out_size)
{
    const float* b1 = (const float*)d_in[0];
    const float* c1 = (const float*)d_in[1];
    const float* p1 = (const float*)d_in[2];
    const float* b2 = (const float*)d_in[3];
    const float* c2 = (const float*)d_in[4];
    const float* p2 = (const float*)d_in[5];
    const float* b3 = (const float*)d_in[6];
    const float* c3 = (const float*)d_in[7];
    const float* p3 = (const float*)d_in[8];

    dim3 tgrid((NANCH + TILE_A - 1) / TILE_A, NB);
    score_transpose_kernel<<<tgrid, 256>>>(c1, p1, c2, p2, c3, p3);
    nms_class_kernel<<<NB * NC, 256>>>(b1, b2, b3);
    topk_final_kernel<<<NB, 1024>>>((float*)d_out);
}

// round 4
// speedup vs baseline: 4.0256x; 1.7228x over previous
#include <cuda_runtime.h>
#include <cstdint>

#define N1 8112
#define N2 2028
#define N3 507
#define NANCH 10647
#define NANCH_P 10656
#define NVEC4 (NANCH_P / 4)        /* 2664 */
#define NVEC4_PAD 2816             /* 11 * 256 */
#define NB 8
#define NC 80
#define KTOP 256
#define CAND 512
#define CBUF 4096
#define MAXPC 100
#define MAXTOT 100
#define SCORE_THR 0.3f
#define IOU_THR 0.5f
#define NEGV -1000000000.0f
#define TILE_A 64

__device__ float  g_scoresT[NB][NC][NANCH_P];
__device__ float  g_sc[NB][NC * MAXPC];
__device__ float4 g_box[NB][NC * MAXPC];
__device__ int    g_cnt[NB][NC];

// ---------------------------------------------------------------------------
// Kernel 0: score compute + transpose. 128 threads, TILE_A=64 anchors/block.
// ---------------------------------------------------------------------------
__global__ __launch_bounds__(128) void score_transpose_kernel(
    const float* __restrict__ c1, const float* __restrict__ p1,
    const float* __restrict__ c2, const float* __restrict__ p2,
    const float* __restrict__ c3, const float* __restrict__ p3)
{
    __shared__ float conf_s[TILE_A];
    __shared__ float tile[TILE_A][NC + 1];

    const int b   = blockIdx.y;
    const int t0  = blockIdx.x * TILE_A;
    const int tid = threadIdx.x;

    if (tid < TILE_A) {
        int a = t0 + tid;
        float cv = 0.0f;
        if (a < NANCH) {
            if (a < N1)           cv = c1[b * N1 + a];
            else if (a < N1 + N2) cv = c2[b * N2 + (a - N1)];
            else                  cv = c3[b * N3 + (a - N1 - N2)];
        }
        conf_s[tid] = cv;
    }
    __syncthreads();

    // load: 64 anchors x 20 float4, coalesced
#pragma unroll
    for (int k = 0; k < 10; k++) {
        int idx = tid + k * 128;
        int al = idx / 20;
        int q  = idx - al * 20;
        int a  = t0 + al;
        float4 v = make_float4(0.f, 0.f, 0.f, 0.f);
        if (a < NANCH) {
            const float* pp; int o;
            if (a < N1)           { pp = p1; o = b * N1 + a; }
            else if (a < N1 + N2) { pp = p2; o = b * N2 + (a - N1); }
            else                  { pp = p3; o = b * N3 + (a - N1 - N2); }
            v = *reinterpret_cast<const float4*>(pp + (size_t)o * NC + q * 4);
        }
        float cf = conf_s[al];
        tile[al][q * 4 + 0] = v.x * cf;
        tile[al][q * 4 + 1] = v.y * cf;
        tile[al][q * 4 + 2] = v.z * cf;
        tile[al][q * 4 + 3] = v.w * cf;
    }
    __syncthreads();

    // store: float4 over anchors, coalesced STG.128
#pragma unroll
    for (int k = 0; k < 10; k++) {
        int idx = tid + k * 128;
        int c  = idx >> 4;
        int g  = idx & 15;
        int al = g * 4;
        int a0 = t0 + al;
        if (a0 < NANCH_P) {
            float4 v = make_float4(tile[al][c], tile[al + 1][c],
                                   tile[al + 2][c], tile[al + 3][c]);
            *reinterpret_cast<float4*>(&g_scoresT[b][c][a0]) = v;
        }
    }
}

// ---------------------------------------------------------------------------
// Kernel 1: per-(image,class) NMS with early-stop tiled suppression.
// ---------------------------------------------------------------------------
__global__ __launch_bounds__(256) void nms_class_kernel(
    const float* __restrict__ b1, const float* __restrict__ b2,
    const float* __restrict__ b3)
{
    __shared__ __align__(16) unsigned char ubuf[CBUF * 8];   // 32 KB union
    __shared__ unsigned long long keys[CAND];                 // 4 KB
    __shared__ int hist[256];
    __shared__ int misc[4];
    __shared__ unsigned validm[8];

    unsigned long long* cand = reinterpret_cast<unsigned long long*>(ubuf);
    float*    cy1   = reinterpret_cast<float*>(ubuf);                 // 1 KB
    float*    cx1   = reinterpret_cast<float*>(ubuf + 1024);          // 1 KB
    float*    cy2   = reinterpret_cast<float*>(ubuf + 2048);          // 1 KB
    float*    cx2   = reinterpret_cast<float*>(ubuf + 3072);          // 1 KB
    float*    carea = reinterpret_cast<float*>(ubuf + 4096);          // 1 KB
    float*    csc   = reinterpret_cast<float*>(ubuf + 5120);          // 1 KB
    int*   keptslot = reinterpret_cast<int*>(ubuf + 6144);            // 1 KB
    unsigned* supp2 = reinterpret_cast<unsigned*>(ubuf + 7168);       // 4 KB (2 halves x 128 rows x 4 words)
    unsigned* supp8 = reinterpret_cast<unsigned*>(ubuf + 11264);      // 8 KB (slow path)

    const int b    = blockIdx.x / NC;
    const int c    = blockIdx.x % NC;
    const int tid  = threadIdx.x;
    const int lane = tid & 31;
    const unsigned ltmask = (1u << lane) - 1u;

    hist[tid] = 0;
    if (tid == 0) { misc[0] = 0; misc[2] = 0; }
    keys[tid] = 0ull;
    keys[tid + 256] = 0ull;
    __syncthreads();

    // Phase 1: single global pass: histogram + warp-aggregated append
    const float4* srow4 = reinterpret_cast<const float4*>(&g_scoresT[b][c][0]);
    for (int it = tid; it < NVEC4_PAD; it += 256) {
        float4 v = make_float4(0.f, 0.f, 0.f, 0.f);
        if (it < NVEC4) v = srow4[it];
        float sv[4] = {v.x, v.y, v.z, v.w};
#pragma unroll
        for (int k = 0; k < 4; k++) {
            float s = sv[k];
            bool pred = s > SCORE_THR;
            unsigned m = __ballot_sync(0xFFFFFFFFu, pred);
            if (pred) {
                int bk = (int)((s - SCORE_THR) * (256.0f / 0.7f));
                bk = bk > 255 ? 255 : (bk < 0 ? 0 : bk);
                atomicAdd(&hist[bk], 1);
                int rank = __popc(m & ltmask);
                int base;
                if (rank == 0) base = atomicAdd(&misc[0], __popc(m));
                base = __shfl_sync(m, base, __ffs(m) - 1);
                int pos = base + rank;
                unsigned a = (unsigned)(it * 4 + k);
                if (pos < CBUF)
                    cand[pos] = ((unsigned long long)__float_as_uint(s) << 32)
                                | (unsigned)(~a);
            }
        }
    }
    __syncthreads();

    // Phase 2: cut bucket (largest bb with suffix >= KTOP)
    if (tid < 32) {
        int partial = 0;
#pragma unroll
        for (int k2 = 0; k2 < 8; k2++) partial += hist[tid * 8 + k2];
        int suf = partial;
#pragma unroll
        for (int off = 1; off < 32; off <<= 1) {
            int v = __shfl_down_sync(0xFFFFFFFFu, suf, off);
            if (tid + off < 32) suf += v;
        }
        unsigned bal = __ballot_sync(0xFFFFFFFFu, suf >= KTOP);
        if (bal != 0) {
            int g = 31 - __clz(bal);
            int basev = (g < 31) ? __shfl_sync(0xFFFFFFFFu, suf, g + 1) : 0;
            if (tid == 0) {
                int acc = basev, bb = 8 * g;
                for (int k2 = 7; k2 >= 0; k2--) {
                    acc += hist[8 * g + k2];
                    if (acc >= KTOP) { bb = 8 * g + k2; break; }
                }
                misc[1] = bb;
            }
        } else if (tid == 0) {
            misc[1] = 0;
        }
    }
    __syncthreads();

    // Phase 3: select >= cut bucket into keys[]
    const int bb  = misc[1];
    const int cnt = misc[0] < CBUF ? misc[0] : CBUF;
    const int cntp = (cnt + 255) & ~255;
    for (int it = tid; it < cntp; it += 256) {
        unsigned long long key = (it < cnt) ? cand[it] : 0ull;
        float s = __uint_as_float((unsigned)(key >> 32));
        bool pred = false;
        if (it < cnt) {
            int bk = (int)((s - SCORE_THR) * (256.0f / 0.7f));
            bk = bk > 255 ? 255 : (bk < 0 ? 0 : bk);
            pred = (bk >= bb);
        }
        unsigned m = __ballot_sync(0xFFFFFFFFu, pred);
        if (pred) {
            int rank = __popc(m & ltmask);
            int base;
            if (rank == 0) base = atomicAdd(&misc[2], __popc(m));
            base = __shfl_sync(m, base, __ffs(m) - 1);
            int pos = base + rank;
            if (pos < CAND) keys[pos] = key;
        }
    }
    __syncthreads();

    // Phase 4: bitonic sort 512 descending
    for (int k = 2; k <= CAND; k <<= 1) {
        for (int j = k >> 1; j > 0; j >>= 1) {
            int i = ((tid & ~(j - 1)) << 1) | (tid & (j - 1));
            int p = i | j;
            unsigned long long va = keys[i], vb = keys[p];
            if ((va < vb) == ((i & k) == 0)) { keys[i] = vb; keys[p] = va; }
            __syncthreads();
        }
    }

    // Phase 5: top-256 -> SoA boxes/scores/areas/valid
    unsigned long long mykey = keys[tid];
    bool valid = (mykey != 0ull);
    float sc = __uint_as_float((unsigned)(mykey >> 32));
    float4 bx = make_float4(0.f, 0.f, 0.f, 0.f);
    if (valid) {
        unsigned a = ~(unsigned)(mykey & 0xFFFFFFFFu);
        const float* bp; size_t off;
        if (a < N1)           { bp = b1; off = (size_t)(b * N1 + a) * 4; }
        else if (a < N1 + N2) { bp = b2; off = (size_t)(b * N2 + (a - N1)) * 4; }
        else                  { bp = b3; off = (size_t)(b * N3 + (a - N1 - N2)) * 4; }
        bx = *reinterpret_cast<const float4*>(bp + off);
    }
    cy1[tid] = bx.x; cx1[tid] = bx.y; cy2[tid] = bx.z; cx2[tid] = bx.w;
    carea[tid] = (bx.z - bx.x) * (bx.w - bx.y);
    csc[tid] = sc;
    keptslot[tid] = -1;
    {
        unsigned bal = __ballot_sync(0xFFFFFFFFu, valid);
        if (lane == 0) validm[tid >> 5] = bal;
    }
    __syncthreads();

    // Phase 6a: 128x128 triangle, 2 threads per row (parity split on j)
    {
        const int i = tid & 127;
        const int h = tid >> 7;
        const float y1 = cy1[i], x1 = cx1[i], y2 = cy2[i], x2 = cx2[i];
        const float areai = carea[i];
        unsigned w0 = 0u, w1 = 0u, w2 = 0u, w3 = 0u;
        for (int j = i + 1 + h; j < 128; j += 2) {
            float jy1 = cy1[j], jx1 = cx1[j], jy2 = cy2[j], jx2 = cx2[j];
            float aj = carea[j];
            float iy = fmaxf(fminf(y2, jy2) - fmaxf(y1, jy1), 0.0f);
            float ix = fmaxf(fminf(x2, jx2) - fmaxf(x1, jx1), 0.0f);
            float inter = iy * ix;
            float uni = (areai + aj) - inter;
            if (inter > 0.4f * uni) {
                float iou = inter / uni;
                if (iou > IOU_THR) {
                    unsigned bit = 1u << (j & 31);
                    switch (j >> 5) {
                        case 0: w0 |= bit; break; case 1: w1 |= bit; break;
                        case 2: w2 |= bit; break; default: w3 |= bit; break;
                    }
                }
            }
        }
        *reinterpret_cast<uint4*>(&supp2[tid * 4]) = make_uint4(w0, w1, w2, w3);
    }
    __syncthreads();

    // Phase 7a: fast serial scan over i<128, early stop at count==100
    if (tid == 0) {
        unsigned k0 = validm[0], k1 = validm[1], k2 = validm[2], k3 = validm[3];
        int count = 0;
        bool hit = false;
        for (int w = 0; w < 4 && !hit; w++) {
            unsigned kw = (w == 0) ? k0 : (w == 1) ? k1 : (w == 2) ? k2 : k3;
            unsigned cw = kw;
            while (cw) {
                int bit = __ffs(cw) - 1;
                int i = (w << 5) + bit;
                count++;
                keptslot[i] = count - 1;
                if (count == MAXPC) { hit = true; break; }
                uint4 ra = *reinterpret_cast<const uint4*>(&supp2[i * 4]);
                uint4 rb = *reinterpret_cast<const uint4*>(&supp2[(i + 128) * 4]);
                k0 &= ~(ra.x | rb.x); k1 &= ~(ra.y | rb.y);
                k2 &= ~(ra.z | rb.z); k3 &= ~(ra.w | rb.w);
                unsigned above = (bit == 31) ? 0u : (0xFFFFFFFFu << (bit + 1));
                kw = (w == 0) ? k0 : (w == 1) ? k1 : (w == 2) ? k2 : k3;
                cw = kw & above;
            }
        }
        misc[3] = hit ? 1 : 0;
        if (hit) { misc[2] = MAXPC; g_cnt[b][c] = MAXPC; }
    }
    __syncthreads();

    // Slow path (rare): full matrix + full rescan
    if (!misc[3]) {
        const int i = tid;
        const float y1 = cy1[i], x1 = cx1[i], y2 = cy2[i], x2 = cx2[i];
        const float areai = carea[i];
        unsigned words[8];
#pragma unroll
        for (int w = 0; w < 8; w++) words[w] = 0u;
        for (int j = i + 1; j < KTOP; j++) {
            float jy1 = cy1[j], jx1 = cx1[j], jy2 = cy2[j], jx2 = cx2[j];
            float aj = carea[j];
            float iy = fmaxf(fminf(y2, jy2) - fmaxf(y1, jy1), 0.0f);
            float ix = fmaxf(fminf(x2, jx2) - fmaxf(x1, jx1), 0.0f);
            float inter = iy * ix;
            float uni = (areai + aj) - inter;
            if (inter > 0.4f * uni) {
                float iou = inter / uni;
                if (iou > IOU_THR) words[j >> 5] |= (1u << (j & 31));
            }
        }
        uint4* sp = reinterpret_cast<uint4*>(&supp8[i * 8]);
        sp[0] = make_uint4(words[0], words[1], words[2], words[3]);
        sp[1] = make_uint4(words[4], words[5], words[6], words[7]);
        __syncthreads();
        if (tid == 0) {
            unsigned kk[8];
#pragma unroll
            for (int w = 0; w < 8; w++) kk[w] = validm[w];
            int count = 0;
            for (int w = 0; w < 8; w++) {
                unsigned cw = kk[w];
                while (cw) {
                    int bit = __ffs(cw) - 1;
                    int i2 = (w << 5) + bit;
                    count++;
                    if (count <= MAXPC) keptslot[i2] = count - 1;
                    uint4 r0 = *reinterpret_cast<const uint4*>(&supp8[i2 * 8]);
                    uint4 r1 = *reinterpret_cast<const uint4*>(&supp8[i2 * 8 + 4]);
                    kk[0] &= ~r0.x; kk[1] &= ~r0.y; kk[2] &= ~r0.z; kk[3] &= ~r0.w;
                    kk[4] &= ~r1.x; kk[5] &= ~r1.y; kk[6] &= ~r1.z; kk[7] &= ~r1.w;
                    unsigned above = (bit == 31) ? 0u : (0xFFFFFFFFu << (bit + 1));
                    cw = kk[w] & above;
                }
            }
            int cc = count > MAXPC ? MAXPC : count;
            misc[2] = cc;
            g_cnt[b][c] = cc;
        }
        __syncthreads();
    }

    // Epilogue: kept writes + NEG tail so topk can stream g_sc blindly
    {
        int r = keptslot[tid];
        if (r >= 0 && r < MAXPC) {
            g_sc[b][c * MAXPC + r]  = csc[tid];
            g_box[b][c * MAXPC + r] = bx;
        }
        int cf = misc[2];
        if (tid >= cf && tid < MAXPC) g_sc[b][c * MAXPC + tid] = NEGV;
    }
}

// ---------------------------------------------------------------------------
// Kernel 2: per-image top-100. 256 threads, vectorized streaming.
// ---------------------------------------------------------------------------
#define FBINS 2048
#define FCAND 512

__global__ __launch_bounds__(256) void topk_final_kernel(float* __restrict__ out)
{
    __shared__ int hist2[FBINS];
    __shared__ unsigned long long keys2[FCAND];
    __shared__ int gsum[64];
    __shared__ int misc2[4];

    const int b   = blockIdx.x;
    const int tid = threadIdx.x;

#pragma unroll
    for (int k = 0; k < 8; k++) hist2[tid + k * 256] = 0;
    keys2[tid] = 0ull;
    keys2[tid + 256] = 0ull;
    if (tid == 0) { misc2[0] = 0; misc2[2] = 0; }
    __syncthreads();

    if (tid < NC) atomicAdd(&misc2[2], g_cnt[b][tid]);

    const float4* gs4 = reinterpret_cast<const float4*>(&g_sc[b][0]);
#pragma unroll
    for (int k = 0; k < 8; k++) {
        int t = tid + k * 256;                 // 2000 float4 = 8000 floats
        if (t < (NC * MAXPC) / 4) {
            float4 v = gs4[t];
            float sv[4] = {v.x, v.y, v.z, v.w};
#pragma unroll
            for (int q = 0; q < 4; q++) {
                float s = sv[q];
                if (s > SCORE_THR) {
                    int bk = (int)((s - SCORE_THR) * ((float)FBINS / 0.7f));
                    bk = bk > FBINS - 1 ? FBINS - 1 : (bk < 0 ? 0 : bk);
                    atomicAdd(&hist2[bk], 1);
                }
            }
        }
    }
    __syncthreads();

    if (tid < 64) {
        int s = 0;
#pragma unroll
        for (int k = 0; k < 32; k++) s += hist2[tid * 32 + k];
        gsum[tid] = s;
    }
    __syncthreads();
    if (tid == 0) {
        int acc = 0, g = -1, bbv = 0;
        for (int i = 63; i >= 0; i--) {
            if (acc + gsum[i] >= MAXTOT) { g = i; break; }
            acc += gsum[i];
        }
        if (g >= 0) {
            for (int k = 31; k >= 0; k--) {
                acc += hist2[g * 32 + k];
                if (acc >= MAXTOT) { bbv = g * 32 + k; break; }
            }
        }
        misc2[1] = bbv;
        misc2[0] = 0;
    }
    __syncthreads();

    const int bb = misc2[1];
#pragma unroll
    for (int k = 0; k < 8; k++) {
        int t = tid + k * 256;
        if (t < (NC * MAXPC) / 4) {
            float4 v = gs4[t];
            float sv[4] = {v.x, v.y, v.z, v.w};
#pragma unroll
            for (int q = 0; q < 4; q++) {
                float s = sv[q];
                if (s > SCORE_THR) {
                    int bk = (int)((s - SCORE_THR) * ((float)FBINS / 0.7f));
                    bk = bk > FBINS - 1 ? FBINS - 1 : (bk < 0 ? 0 : bk);
                    if (bk >= bb) {
                        int pos = atomicAdd(&misc2[0], 1);
                        if (pos < FCAND) {
                            unsigned s_idx = (unsigned)(t * 4 + q);
                            keys2[pos] = ((unsigned long long)__float_as_uint(s) << 32)
                                         | (unsigned)(~s_idx);
                        }
                    }
                }
            }
        }
    }
    __syncthreads();

    // bitonic sort 512 descending (256 comparators = 256 threads)
    for (int k = 2; k <= FCAND; k <<= 1) {
        for (int j = k >> 1; j > 0; j >>= 1) {
            int i = ((tid & ~(j - 1)) << 1) | (tid & (j - 1));
            int p = i | j;
            unsigned long long va = keys2[i], vb = keys2[p];
            if ((va < vb) == ((i & k) == 0)) { keys2[i] = vb; keys2[p] = va; }
            __syncthreads();
        }
    }

    float* ob = out;                    // [8][100][4]
    float* os = out + NB * MAXTOT * 4;  // [8][100]
    float* oc = os + NB * MAXTOT;       // [8][100]
    float* on = oc + NB * MAXTOT;       // [8]

    if (tid < MAXTOT) {
        unsigned long long key = keys2[tid];
        float sc = 0.0f, cl = 0.0f;
        float bx0 = 0.f, bx1 = 0.f, bx2 = 0.f, bx3 = 0.f;
        if (key != 0ull) {
            sc = __uint_as_float((unsigned)(key >> 32));
            unsigned s = ~(unsigned)(key & 0xFFFFFFFFu);
            cl = (float)(s / MAXPC);
            float4 bbx = g_box[b][s];
            bx0 = fminf(fmaxf(bbx.x, 0.0f), 1.0f);
            bx1 = fminf(fmaxf(bbx.y, 0.0f), 1.0f);
            bx2 = fminf(fmaxf(bbx.z, 0.0f), 1.0f);
            bx3 = fminf(fmaxf(bbx.w, 0.0f), 1.0f);
        }
        size_t base = (size_t)(b * MAXTOT + tid) * 4;
        ob[base + 0] = bx0; ob[base + 1] = bx1; ob[base + 2] = bx2; ob[base + 3] = bx3;
        os[b * MAXTOT + tid] = sc;
        oc[b * MAXTOT + tid] = cl;
    }
    if (tid == 0) {
        int tot = misc2[2];
        on[b] = (float)(tot > MAXTOT ? MAXTOT : tot);
    }
}

extern "C" void kernel_launch(void* const* d_in, const int* in_sizes, int n_in,
                              void* d_out, int out_size)
{
    const float* b1 = (const float*)d_in[0];
    const float* c1 = (const float*)d_in[1];
    const float* p1 = (const float*)d_in[2];
    const float* b2 = (const float*)d_in[3];
    const float* c2 = (const float*)d_in[4];
    const float* p2 = (const float*)d_in[5];
    const float* b3 = (const float*)d_in[6];
    const float* c3 = (const float*)d_in[7];
    const float* p3 = (const float*)d_in[8];

    dim3 tgrid((NANCH + TILE_A - 1) / TILE_A, NB);
    score_transpose_kernel<<<tgrid, 128>>>(c1, p1, c2, p2, c3, p3);
    nms_class_kernel<<<NB * NC, 256>>>(b1, b2, b3);
    topk_final_kernel<<<NB, 256>>>((float*)d_out);
}